// round 16
// baseline (speedup 1.0000x reference)
#include <cuda_runtime.h>
#include <cstdint>

#define EMBED 768
#define QKV3  (3*EMBED)
#define HEADS 12
#define DH    64
#define NB    2
#define SEQ   2048
#define MROWS (NB*SEQ)          // 4096

// Scratch (no allocations allowed)
__device__ uint32_t g_xt [(size_t)MROWS*EMBED];   // x, tf32 bits, pair-interleaved
__device__ uint32_t g_yt [(size_t)MROWS*EMBED];   // attn out, tf32, interleaved
__device__ uint32_t g_wqt[(size_t)QKV3*EMBED];    // w_qkv^T [n][k], tf32, interleaved
__device__ uint32_t g_wpt[(size_t)EMBED*EMBED];   // w_proj^T
__device__ uint32_t g_qkt[(size_t)MROWS*QKV3];    // Q(scaled)+K+V, tf32, interleaved d
__device__ uint32_t g_vg [(size_t)NB*HEADS*DH*SEQ]; // V^T per head: [bh][d][t-interleaved]

// ---------------- helpers ----------------
__device__ __forceinline__ uint32_t f2tf(float f) {
    uint32_t u;
    asm("cvt.rna.tf32.f32 %0, %1;" : "=r"(u) : "f"(f));
    return u;
}
__device__ __forceinline__ void mma_tf32(float* d, const uint32_t* a, const uint32_t* b) {
    asm volatile(
        "mma.sync.aligned.m16n8k8.row.col.f32.tf32.tf32.f32 "
        "{%0,%1,%2,%3}, {%4,%5,%6,%7}, {%8,%9}, {%0,%1,%2,%3};"
        : "+f"(d[0]), "+f"(d[1]), "+f"(d[2]), "+f"(d[3])
        : "r"(a[0]), "r"(a[1]), "r"(a[2]), "r"(a[3]), "r"(b[0]), "r"(b[1]));
}
__device__ __forceinline__ float ex2(float x) {
    float r;
    asm("ex2.approx.f32 %0, %1;" : "=f"(r) : "f"(x));
    return r;
}
__device__ __forceinline__ uint32_t smem_addr32(const void* p) {
    uint32_t a;
    asm("{ .reg .u64 x; cvta.to.shared.u64 x, %1; cvt.u32.u64 %0, x; }" : "=r"(a) : "l"(p));
    return a;
}
#define CP16(d, s) asm volatile("cp.async.cg.shared.global [%0], [%1], 16;" :: "r"(d), "l"(s) : "memory")
#define CPCOMMIT() asm volatile("cp.async.commit_group;" ::: "memory")
#define CPWAIT1()  asm volatile("cp.async.wait_group 1;" ::: "memory")
#define CPWAIT0()  asm volatile("cp.async.wait_group 0;" ::: "memory")

// ---------------- prologue converters ----------------
__global__ void cvt_x(const float* __restrict__ src, uint32_t* __restrict__ dst) {
    int tid = blockIdx.x * 256 + threadIdx.x;
    const float* s = src + (size_t)tid * 8;
    float4 a = *(const float4*)(s);
    float4 b = *(const float4*)(s + 4);
    uint32_t* d = dst + (size_t)tid * 8;
    *(uint4*)(d)     = make_uint4(f2tf(a.x), f2tf(b.x), f2tf(a.y), f2tf(b.y));
    *(uint4*)(d + 4) = make_uint4(f2tf(a.z), f2tf(b.z), f2tf(a.w), f2tf(b.w));
}
__global__ void cvt_w(const float* __restrict__ src, uint32_t* __restrict__ dst, int N) {
    int tid = blockIdx.x * 256 + threadIdx.x;
    if (tid >= N * (EMBED / 8)) return;
    int n = tid % N, kg = tid / N;
    const float* s = src + (size_t)(kg * 8) * N + n;
    float v[8];
    #pragma unroll
    for (int j = 0; j < 8; j++) v[j] = s[(size_t)j * N];
    uint32_t* d = dst + (size_t)n * EMBED + kg * 8;
    *(uint4*)(d)     = make_uint4(f2tf(v[0]), f2tf(v[4]), f2tf(v[1]), f2tf(v[5]));
    *(uint4*)(d + 4) = make_uint4(f2tf(v[2]), f2tf(v[6]), f2tf(v[3]), f2tf(v[7]));
}

// V transpose: qkt V-region [t][d-interleaved] -> vg [bh][d][t-interleaved]
__global__ void vtrans(const uint32_t* __restrict__ qkt, uint32_t* __restrict__ vg) {
    __shared__ uint32_t sm[64][68];
    const int t0 = blockIdx.x * 64, h = blockIdx.y, b = blockIdx.z;
    const int tid = threadIdx.x;
    {
        const int tr = tid >> 2, c16 = (tid & 3) * 16;
        const uint32_t* src = qkt + (size_t)(b * SEQ + t0 + tr) * QKV3
                                   + 2 * EMBED + h * DH + c16;
        #pragma unroll
        for (int c = 0; c < 16; c++) {
            int p = c16 + c, grp = p & ~7, q = p & 7;
            int dl = grp + ((q & 1) ? (q + 7) / 2 : q / 2);   // phys -> logical
            sm[tr][dl] = src[c];
        }
    }
    __syncthreads();
    {
        const int dr = tid >> 2, c16 = (tid & 3) * 16;
        uint32_t* dst = vg + ((size_t)((b * HEADS + h) * DH + dr)) * SEQ + t0 + c16;
        #pragma unroll
        for (int c = 0; c < 16; c++) {
            int p = c16 + c, grp = p & ~7, q = p & 7;
            int tl = grp + ((q & 1) ? (q + 7) / 2 : q / 2);
            dst[c] = sm[tl][dr];
        }
    }
}

// ---------- GEMM mainloop: CTA 128x128, 256 thr, KBLK=32, 2-stage cp.async ----------
// Register-level fragment double-buffer: load ks+1 frags while mma ks.
#define GST 5120u                 // stage stride words (128*40); stride 40 mod32==8
#define G_SMEM (4 * 5120 * 4)     // 81920 B

#define LOADF(bu, kss)                                                          \
    _Pragma("unroll")                                                           \
    for (int mt = 0; mt < 4; mt++) {                                            \
        int r = wm * 64 + mt * 16 + g;                                          \
        uint2 qa = *(uint2*)&As[s][r][(kss) * 8 + 2 * c4];                      \
        uint2 qb = *(uint2*)&As[s][r + 8][(kss) * 8 + 2 * c4];                  \
        af[bu][mt][0] = qa.x; af[bu][mt][1] = qb.x;                             \
        af[bu][mt][2] = qa.y; af[bu][mt][3] = qb.y;                             \
    }                                                                           \
    _Pragma("unroll")                                                           \
    for (int nt = 0; nt < 4; nt++) {                                            \
        int cc = wn * 32 + nt * 8 + g;                                          \
        uint2 kb = *(uint2*)&Bs[s][cc][(kss) * 8 + 2 * c4];                     \
        bf[bu][nt][0] = kb.x; bf[bu][nt][1] = kb.y;                             \
    }

#define GEMM_MAINLOOP(At, Bt)                                                   \
    uint32_t (*As)[128][40] = (uint32_t(*)[128][40])(smg);                      \
    uint32_t (*Bs)[128][40] = (uint32_t(*)[128][40])(smg + 2 * GST);            \
    const int lr = t >> 1, lh = t & 1;                                          \
    const uint32_t* aSrc = At + (size_t)(row0 + lr) * EMBED + lh * 16;          \
    const uint32_t* bSrc = Bt + (size_t)(col0 + lr) * EMBED + lh * 16;          \
    const uint32_t smb = smem_addr32(smg);                                      \
    const uint32_t aD = smb + (uint32_t)(lr * 160 + lh * 64);                   \
    const uint32_t bD = smb + 2u * GST * 4u + (uint32_t)(lr * 160 + lh * 64);   \
    _Pragma("unroll")                                                           \
    for (int p = 0; p < 2; p++) {                                               \
        _Pragma("unroll")                                                       \
        for (int c = 0; c < 4; c++) {                                           \
            CP16(aD + p * GST * 4 + c * 16, aSrc + p * 32 + c * 4);             \
            CP16(bD + p * GST * 4 + c * 16, bSrc + p * 32 + c * 4);             \
        }                                                                       \
        CPCOMMIT();                                                             \
    }                                                                           \
    float acc[4][4][4] = {};                                                    \
    const int nblk = EMBED / 32;                                                \
    for (int blk = 0; blk < nblk; blk++) {                                      \
        const int s = blk & 1;                                                  \
        if (blk + 1 < nblk) CPWAIT1(); else CPWAIT0();                          \
        __syncthreads();                                                        \
        uint32_t af[2][4][4], bf[2][4][2];                                      \
        LOADF(0, 0)                                                             \
        _Pragma("unroll")                                                       \
        for (int ks = 0; ks < 4; ks++) {                                        \
            const int cu = ks & 1;                                              \
            if (ks < 3) { LOADF(cu ^ 1, ks + 1) }                               \
            _Pragma("unroll")                                                   \
            for (int mt = 0; mt < 4; mt++)                                      \
                _Pragma("unroll")                                               \
                for (int nt = 0; nt < 4; nt++)                                  \
                    mma_tf32(acc[mt][nt], af[cu][mt], bf[cu][nt]);              \
        }                                                                       \
        __syncthreads();                                                        \
        if (blk + 2 < nblk) {                                                   \
            _Pragma("unroll")                                                   \
            for (int c = 0; c < 4; c++) {                                       \
                CP16(aD + s * GST * 4 + c * 16, aSrc + (blk + 2) * 32 + c * 4); \
                CP16(bD + s * GST * 4 + c * 16, bSrc + (blk + 2) * 32 + c * 4); \
            }                                                                   \
            CPCOMMIT();                                                         \
        }                                                                       \
    }

// GEMM1: out -> g_qkt (Q scaled; Q/K/V all tf32 d-interleaved, stride QKV3)
__global__ __launch_bounds__(256, 2) void sgemm_qkv(
    const uint32_t* __restrict__ At, const uint32_t* __restrict__ Bt,
    const float* __restrict__ bias, uint32_t* __restrict__ qkt)
{
    extern __shared__ uint32_t smg[];
    const int t = threadIdx.x, lane = t & 31, warp = t >> 5;
    const int wm = warp >> 2, wn = warp & 3;
    const int row0 = blockIdx.y * 128, col0 = blockIdx.x * 128;
    const int g = lane >> 2, c4 = lane & 3;
    GEMM_MAINLOOP(At, Bt)

    const int p0 = ((c4 & 1) << 2) | (c4 >> 1);
    const float sc = (col0 < EMBED) ? 0.125f * 1.44269504f : 1.0f;  // scale Q only

    #pragma unroll
    for (int mt = 0; mt < 4; mt++) {
        int r = row0 + wm * 64 + mt * 16 + g;
        #pragma unroll
        for (int nt = 0; nt < 4; nt++) {
            int cc = col0 + wn * 32 + nt * 8 + c4 * 2;
            float v0 = acc[mt][nt][0] + bias[cc];
            float v1 = acc[mt][nt][1] + bias[cc + 1];
            float v2 = acc[mt][nt][2] + bias[cc];
            float v3 = acc[mt][nt][3] + bias[cc + 1];
            uint32_t* d0 = &qkt[(size_t)r * QKV3 + (cc & ~7) + p0];
            uint32_t* d1 = &qkt[(size_t)(r + 8) * QKV3 + (cc & ~7) + p0];
            d0[0] = f2tf(v0 * sc); d0[2] = f2tf(v1 * sc);
            d1[0] = f2tf(v2 * sc); d1[2] = f2tf(v3 * sc);
        }
    }
}

// GEMM2: fp32 out
__global__ __launch_bounds__(256, 2) void sgemm_out(
    const uint32_t* __restrict__ At, const uint32_t* __restrict__ Bt,
    const float* __restrict__ bias, float* __restrict__ C, int N)
{
    extern __shared__ uint32_t smg[];
    const int t = threadIdx.x, lane = t & 31, warp = t >> 5;
    const int wm = warp >> 2, wn = warp & 3;
    const int row0 = blockIdx.y * 128, col0 = blockIdx.x * 128;
    const int g = lane >> 2, c4 = lane & 3;
    GEMM_MAINLOOP(At, Bt)

    #pragma unroll
    for (int mt = 0; mt < 4; mt++) {
        int r = row0 + wm * 64 + mt * 16 + g;
        #pragma unroll
        for (int nt = 0; nt < 4; nt++) {
            int cc = col0 + wn * 32 + nt * 8 + c4 * 2;
            float b0 = bias[cc], b1 = bias[cc + 1];
            *(float2*)&C[(size_t)r * N + cc]       = make_float2(acc[mt][nt][0] + b0, acc[mt][nt][1] + b1);
            *(float2*)&C[(size_t)(r + 8) * N + cc] = make_float2(acc[mt][nt][2] + b0, acc[mt][nt][3] + b1);
        }
    }
}

// ---------- Flash attention: q-tile 128, 256 thr, pipelined cp.async K/V ----------
#define QTILE 128
#define KTILE 64
#define AST 72
#define SM_Q 0
#define SM_K (QTILE*AST)
#define SM_V (SM_K + KTILE*AST)
#define SM_P (SM_V + DH*AST)
#define ATTN_W (SM_P + QTILE*AST)

__global__ __launch_bounds__(256, 2) void attn_tf32(
    const uint32_t* __restrict__ qk, const uint32_t* __restrict__ vg,
    uint32_t* __restrict__ yt)
{
    extern __shared__ uint32_t sm[];
    uint32_t (*Qs)[AST] = (uint32_t(*)[AST])(sm + SM_Q);
    uint32_t (*Ks)[AST] = (uint32_t(*)[AST])(sm + SM_K);
    uint32_t (*Vt)[AST] = (uint32_t(*)[AST])(sm + SM_V);
    uint32_t (*Ps)[AST] = (uint32_t(*)[AST])(sm + SM_P);

    const int qtb = gridDim.x - 1 - blockIdx.x;    // heavy tiles first
    const int h = blockIdx.y, b = blockIdx.z;
    const int t = threadIdx.x, lane = t & 31, warp = t >> 5;
    const int g = lane >> 2, c4 = lane & 3;
    const int q0 = qtb * QTILE;
    const int rb = warp * 16;
    const float FM2 = 12.0f * 1.44269504f;

    const uint32_t smb = smem_addr32(sm);
    const int m0 = b * SEQ + q0;
    const size_t vbase = (size_t)(b * HEADS + h) * DH * SEQ;

    const int qrow = t >> 1, qh = t & 1;
    const int krow = t >> 2, kq = t & 3;
    const uint32_t qDst = smb + SM_Q * 4 + (uint32_t)(qrow * (AST * 4) + qh * 128);
    const uint32_t kDst = smb + SM_K * 4 + (uint32_t)(krow * (AST * 4) + kq * 64);
    const uint32_t vDst = smb + SM_V * 4 + (uint32_t)(krow * (AST * 4) + kq * 64);
    const uint32_t* qSrc  = qk + (size_t)(m0 + qrow) * QKV3 + h * DH + qh * 32;
    const uint32_t* kBase = qk + (size_t)(b * SEQ + krow) * QKV3 + EMBED + h * DH + kq * 16;
    const uint32_t* vBase = vg + vbase + (size_t)krow * SEQ + kq * 16;

    #pragma unroll
    for (int c = 0; c < 8; c++) CP16(qDst + c * 16, qSrc + c * 4);
    CPCOMMIT();
    #pragma unroll
    for (int c = 0; c < 4; c++) CP16(kDst + c * 16, kBase + c * 4);
    CPCOMMIT();
    #pragma unroll
    for (int c = 0; c < 4; c++) CP16(vDst + c * 16, vBase + c * 4);
    CPCOMMIT();

    float oacc[8][4] = {};
    float l0 = 0.f, l1 = 0.f;

    const int ktmax = 2 * qtb + 1;
    for (int kt = 0; kt <= ktmax; kt++) {
        const int k0 = kt * KTILE;
        CPWAIT1();          // Q + K(kt) complete; V(kt) may be in flight
        __syncthreads();

        float sacc[8][4] = {};
        #pragma unroll
        for (int ds = 0; ds < 8; ds++) {
            uint32_t af[4];
            int kk2 = ds * 8 + 2 * c4;
            uint2 qa = *(uint2*)&Qs[rb + g][kk2];
            uint2 qb = *(uint2*)&Qs[rb + g + 8][kk2];
            af[0] = qa.x; af[1] = qb.x; af[2] = qa.y; af[3] = qb.y;
            #pragma unroll
            for (int nt = 0; nt < 8; nt++) {
                uint2 kb = *(uint2*)&Ks[nt * 8 + g][kk2];
                uint32_t bf[2] = {kb.x, kb.y};
                mma_tf32(sacc[nt], af, bf);
            }
        }
        __syncthreads();
        if (kt < ktmax) {
            const uint32_t* kS = kBase + (size_t)(k0 + KTILE) * QKV3;
            #pragma unroll
            for (int c = 0; c < 4; c++) CP16(kDst + c * 16, kS + c * 4);
            CPCOMMIT();
        }

        const int row0g = q0 + rb + g, row1g = row0g + 8;
        if (k0 + KTILE - 1 > q0) {
            #pragma unroll
            for (int nt = 0; nt < 8; nt++) {
                int cg = k0 + nt * 8 + c4 * 2;
                if (cg     > row0g) sacc[nt][0] = -1e30f;
                if (cg + 1 > row0g) sacc[nt][1] = -1e30f;
                if (cg     > row1g) sacc[nt][2] = -1e30f;
                if (cg + 1 > row1g) sacc[nt][3] = -1e30f;
            }
        }

        const int p0 = ((c4 & 1) << 2) | (c4 >> 1);
        float s0 = 0.f, s1 = 0.f;
        #pragma unroll
        for (int nt = 0; nt < 8; nt++) {
            float e0 = ex2(sacc[nt][0] - FM2);
            float e1 = ex2(sacc[nt][1] - FM2);
            float e2 = ex2(sacc[nt][2] - FM2);
            float e3 = ex2(sacc[nt][3] - FM2);
            s0 += e0 + e1; s1 += e2 + e3;
            Ps[rb + g][nt * 8 + p0]         = f2tf(e0);
            Ps[rb + g][nt * 8 + p0 + 2]     = f2tf(e1);
            Ps[rb + g + 8][nt * 8 + p0]     = f2tf(e2);
            Ps[rb + g + 8][nt * 8 + p0 + 2] = f2tf(e3);
        }
        s0 += __shfl_xor_sync(0xffffffffu, s0, 1);
        s0 += __shfl_xor_sync(0xffffffffu, s0, 2);
        s1 += __shfl_xor_sync(0xffffffffu, s1, 1);
        s1 += __shfl_xor_sync(0xffffffffu, s1, 2);
        l0 += s0; l1 += s1;
        __syncwarp();

        if (kt < ktmax) CPWAIT1(); else CPWAIT0();   // V(kt) complete
        __syncthreads();

        #pragma unroll
        for (int ks = 0; ks < 8; ks++) {
            uint32_t af[4];
            int kk2 = ks * 8 + 2 * c4;
            uint2 pa = *(uint2*)&Ps[rb + g][kk2];
            uint2 pb = *(uint2*)&Ps[rb + g + 8][kk2];
            af[0] = pa.x; af[1] = pb.x; af[2] = pa.y; af[3] = pb.y;
            #pragma unroll
            for (int nt = 0; nt < 8; nt++) {
                uint2 vb = *(uint2*)&Vt[nt * 8 + g][kk2];
                uint32_t bf[2] = {vb.x, vb.y};
                mma_tf32(oacc[nt], af, bf);
            }
        }
        __syncthreads();
        if (kt < ktmax) {
            const uint32_t* vS = vBase + (k0 + KTILE);
            #pragma unroll
            for (int c = 0; c < 4; c++) CP16(vDst + c * 16, vS + c * 4);
            CPCOMMIT();
        }
    }

    float inv0 = 1.f / l0, inv1 = 1.f / l1;
    const int row0g = q0 + rb + g, row1g = row0g + 8;
    const int p0 = ((c4 & 1) << 2) | (c4 >> 1);
    #pragma unroll
    for (int nt = 0; nt < 8; nt++) {
        uint32_t* y0 = &yt[(size_t)(b * SEQ + row0g) * EMBED + h * DH + nt * 8];
        uint32_t* y1 = &yt[(size_t)(b * SEQ + row1g) * EMBED + h * DH + nt * 8];
        y0[p0]     = f2tf(oacc[nt][0] * inv0);
        y0[p0 + 2] = f2tf(oacc[nt][1] * inv0);
        y1[p0]     = f2tf(oacc[nt][2] * inv1);
        y1[p0 + 2] = f2tf(oacc[nt][3] * inv1);
    }
}

extern "C" void kernel_launch(void* const* d_in, const int* in_sizes, int n_in,
                              void* d_out, int out_size)
{
    const float* x      = (const float*)d_in[0];
    const float* w_qkv  = (const float*)d_in[1];
    const float* b_qkv  = (const float*)d_in[2];
    const float* w_proj = (const float*)d_in[3];
    const float* b_proj = (const float*)d_in[4];
    float* out = (float*)d_out;

    uint32_t *xt, *ytp, *wqt, *wpt, *qkt, *vgp;
    cudaGetSymbolAddress((void**)&xt,  g_xt);
    cudaGetSymbolAddress((void**)&ytp, g_yt);
    cudaGetSymbolAddress((void**)&wqt, g_wqt);
    cudaGetSymbolAddress((void**)&wpt, g_wpt);
    cudaGetSymbolAddress((void**)&qkt, g_qkt);
    cudaGetSymbolAddress((void**)&vgp, g_vg);

    cudaFuncSetAttribute(sgemm_qkv, cudaFuncAttributeMaxDynamicSharedMemorySize, G_SMEM);
    cudaFuncSetAttribute(sgemm_out, cudaFuncAttributeMaxDynamicSharedMemorySize, G_SMEM);
    const int attn_smem = ATTN_W * (int)sizeof(uint32_t);   // 110592 B
    cudaFuncSetAttribute(attn_tf32, cudaFuncAttributeMaxDynamicSharedMemorySize, attn_smem);

    cvt_x<<<(MROWS * (EMBED/8)) / 256, 256>>>(x, xt);
    cvt_w<<<(QKV3  * (EMBED/8) + 255) / 256, 256>>>(w_qkv, wqt, QKV3);
    cvt_w<<<(EMBED * (EMBED/8) + 255) / 256, 256>>>(w_proj, wpt, EMBED);

    sgemm_qkv<<<dim3(QKV3/128, MROWS/128), 256, G_SMEM>>>(xt, wqt, b_qkv, qkt);
    vtrans<<<dim3(SEQ/64, HEADS, NB), 256>>>(qkt, vgp);
    attn_tf32<<<dim3(SEQ/QTILE, HEADS, NB), 256, attn_smem>>>(qkt, vgp, ytp);
    sgemm_out<<<dim3(EMBED/128, MROWS/128), 256, G_SMEM>>>(ytp, wpt, b_proj, out, EMBED);
}